// round 12
// baseline (speedup 1.0000x reference)
#include <cuda_runtime.h>
#include <cuda_fp16.h>
#include <cstdint>

#define BB 2
#define CC 128
#define NN 4096
#define LOG2E 1.4426950408889634f

// Device scratch
__device__ __half g_qh[BB * NN * CC];      // [b][n][c_perm]  fp16, pre-scaled by log2e
__device__ __half g_kh[BB * NN * CC];      // [b][n][c_perm]  fp16
__device__ __half g_vh[BB * CC * NN];      // [b][c][n_perm]  fp16
__device__ float g_part[2 * BB * CC * NN]; // [half][b][c][n] partial O
__device__ float g_lsum[2 * BB * NN];      // [half][b][n] partial row sums

// ============================ helpers ============================
__device__ __forceinline__ uint32_t smem_u32(const void* p) {
    uint32_t a;
    asm("{ .reg .u64 t; cvta.to.shared.u64 t, %1; cvt.u32.u64 %0, t; }"
        : "=r"(a) : "l"(p));
    return a;
}
__device__ __forceinline__ uint32_t ex2_h2(uint32_t x) {
    uint32_t r;
    asm("ex2.approx.f16x2 %0, %1;" : "=r"(r) : "r"(x));
    return r;
}
__device__ __forceinline__ uint32_t pack_h2(float lo, float hi) {
    __half2 h = __floats2half2_rn(lo, hi);
    return *reinterpret_cast<uint32_t*>(&h);
}

#define MMA_F16(d, a, b0, b1) \
    asm volatile("mma.sync.aligned.m16n8k16.row.col.f32.f16.f16.f32 " \
        "{%0,%1,%2,%3}, {%4,%5,%6,%7}, {%8,%9}, {%0,%1,%2,%3};" \
        : "+f"((d)[0]), "+f"((d)[1]), "+f"((d)[2]), "+f"((d)[3]) \
        : "r"((a)[0]), "r"((a)[1]), "r"((a)[2]), "r"((a)[3]), "r"(b0), "r"(b1))

#define CPA(dst, src) \
    asm volatile("cp.async.cg.shared.global [%0], [%1], 16;" :: "r"(dst), "l"(src))
#define CPA_COMMIT asm volatile("cp.async.commit_group;" ::: "memory")
#define CPA_WAIT0  asm volatile("cp.async.wait_group 0;" ::: "memory")
#define CPA_WAIT1  asm volatile("cp.async.wait_group 1;" ::: "memory")

// ============================ QKV: merged 1-wave, 3xFP16 split GEMM, permuted outputs ============================
#define WS 132
#define OFF_W1  16896
#define OFF_XF  33792
#define OFF_XHI 43008
#define OFF_XLO 47360
#define SMEM_QKV (51712 * 4)
#define INV64 0.015625f

__global__ __launch_bounds__(256, 1)
void qkv5(const float* __restrict__ x,
          const float* __restrict__ Wq, const float* __restrict__ bq,
          const float* __restrict__ Wk, const float* __restrict__ bk,
          const float* __restrict__ Wv, const float* __restrict__ bv) {
    extern __shared__ float sm[];
    uint32_t sbase = smem_u32(sm);

    int n0 = blockIdx.x * 64;
    int b = blockIdx.y;
    const float* xb = x + (size_t)b * CC * NN;
    const float* Bm[3] = {bq, bk, bv};

    int tid = threadIdx.x;
    int w = tid >> 5, lane = tid & 31;
    int g = lane >> 2, t = lane & 3;
    int crow = w * 16 + g;

    // ---- prologue: W0(Wq) | X | W1(Wk) in separate groups ----
    #pragma unroll
    for (int it = 0; it < 16; it++) {
        int i = tid + it * 256;
        int r = i >> 5, c4 = (i & 31) << 2;
        CPA(sbase + (uint32_t)(r * WS + c4) * 4, Wq + (size_t)r * CC + c4);
    }
    CPA_COMMIT;
    #pragma unroll
    for (int it = 0; it < 8; it++) {
        int i = tid + it * 256;
        int r = i >> 4, n4 = (i & 15) << 2;
        CPA(sbase + (uint32_t)(OFF_XF + r * 72 + n4) * 4, xb + (size_t)r * NN + n0 + n4);
    }
    CPA_COMMIT;
    #pragma unroll
    for (int it = 0; it < 16; it++) {
        int i = tid + it * 256;
        int r = i >> 5, c4 = (i & 31) << 2;
        CPA(sbase + (uint32_t)(OFF_W1 + r * WS + c4) * 4, Wk + (size_t)r * CC + c4);
    }
    CPA_COMMIT;

    CPA_WAIT1;
    __syncthreads();

    // ---- convert X -> transposed fp16 hi/lo tiles [n][k], stride 136 halves ----
    {
        int n = tid >> 2;
        int kbase = (tid & 3) * 32;
        uint32_t* XhiT = (uint32_t*)sm + OFF_XHI;
        uint32_t* XloT = (uint32_t*)sm + OFF_XLO;
        #pragma unroll
        for (int j = 0; j < 16; j++) {
            int k = kbase + 2 * j;
            float f0 = sm[OFF_XF + k * 72 + n];
            float f1 = sm[OFF_XF + (k + 1) * 72 + n];
            __half h0 = __float2half_rn(f0), h1 = __float2half_rn(f1);
            uint32_t hi = pack_h2(__half2float(h0), __half2float(h1));
            uint32_t lo = pack_h2(f0 - __half2float(h0), f1 - __half2float(h1));
            XhiT[n * 68 + (kbase >> 1) + j] = hi;
            XloT[n * 68 + (kbase >> 1) + j] = lo;
        }
    }
    __syncthreads();

    const uint32_t* Xhi = (const uint32_t*)sm + OFF_XHI;
    const uint32_t* Xlo = (const uint32_t*)sm + OFF_XLO;

    #pragma unroll 1
    for (int m = 0; m < 3; m++) {
        const float* Wb = sm + ((m & 1) ? OFF_W1 : 0);

        // ---- hoist W fp16 hi/lo A-frags (scaled x64) ----
        uint32_t wa_hi[8][4], wa_lo[8][4];
        #pragma unroll
        for (int ko = 0; ko < 8; ko++) {
            #pragma unroll
            for (int q = 0; q < 4; q++) {
                int row = crow + ((q & 1) ? 8 : 0);
                int kk = ko * 16 + 2 * t + ((q >> 1) ? 8 : 0);
                float2 p = *(const float2*)&Wb[row * WS + kk];
                p.x *= 64.0f; p.y *= 64.0f;
                __half h0 = __float2half_rn(p.x), h1 = __float2half_rn(p.y);
                wa_hi[ko][q] = pack_h2(__half2float(h0), __half2float(h1));
                wa_lo[ko][q] = pack_h2(p.x - __half2float(h0), p.y - __half2float(h1));
            }
        }
        __syncthreads();

        if (m == 0) {
            #pragma unroll
            for (int it = 0; it < 16; it++) {
                int i = tid + it * 256;
                int r = i >> 5, c4 = (i & 31) << 2;
                CPA(sbase + (uint32_t)(r * WS + c4) * 4, Wv + (size_t)r * CC + c4);
            }
            CPA_COMMIT;
        }

        // ---- 3xFP16 GEMM ----
        float acc[8][4] = {};
        #pragma unroll
        for (int ko = 0; ko < 8; ko++) {
            #pragma unroll
            for (int nt = 0; nt < 8; nt++) {
                int i0 = (nt * 8 + g) * 68 + ko * 8 + t;
                uint32_t bh0 = Xhi[i0], bh1 = Xhi[i0 + 4];
                uint32_t bl0 = Xlo[i0], bl1 = Xlo[i0 + 4];
                MMA_F16(acc[nt], wa_lo[ko], bh0, bh1);
                MMA_F16(acc[nt], wa_hi[ko], bl0, bl1);
                MMA_F16(acc[nt], wa_hi[ko], bh0, bh1);
            }
        }
        __syncthreads();

        const float* bias = Bm[m];
        float b0v = bias[crow], b1v = bias[crow + 8];
        float qs = (m == 0) ? LOG2E : 1.0f;
        __half* st_h = (__half*)(sm + OFF_XF);

        if (m != 2) {
            // q,k: stage [n][c_perm]: within 16-c blocks, order (0,1,8,9, 2,3,10,11, ...)
            int c_lo = w * 16 + ((g >> 1) << 2) + (g & 1);
            int c_hi = c_lo + 2;
            #pragma unroll
            for (int nt = 0; nt < 8; nt++) {
                int n = nt * 8 + 2 * t;
                st_h[n * 136 + c_lo]       = __float2half_rn((acc[nt][0] * INV64 + b0v) * qs);
                st_h[(n + 1) * 136 + c_lo] = __float2half_rn((acc[nt][1] * INV64 + b0v) * qs);
                st_h[n * 136 + c_hi]       = __float2half_rn((acc[nt][2] * INV64 + b1v) * qs);
                st_h[(n + 1) * 136 + c_hi] = __float2half_rn((acc[nt][3] * INV64 + b1v) * qs);
            }
            __syncthreads();
            __half* out = ((m == 0) ? g_qh : g_kh) + ((size_t)b * NN + n0) * CC;
            #pragma unroll
            for (int it = 0; it < 4; it++) {
                int i = tid + it * 256;
                int r = i >> 4, c8 = (i & 15) << 3;
                *(uint4*)(out + (size_t)r * CC + c8) = *(uint4*)&st_h[r * 136 + c8];
            }
        } else {
            // v: stage [c][n_perm]: keys permuted within 16-key blocks
            #pragma unroll
            for (int nt = 0; nt < 8; nt++) {
                int n_pos = ((nt >> 1) << 4) + 4 * t + ((nt & 1) ? 2 : 0);
                *(__half2*)&st_h[crow * 72 + n_pos] =
                    __floats2half2_rn(acc[nt][0] * INV64 + b0v, acc[nt][1] * INV64 + b0v);
                *(__half2*)&st_h[(crow + 8) * 72 + n_pos] =
                    __floats2half2_rn(acc[nt][2] * INV64 + b1v, acc[nt][3] * INV64 + b1v);
            }
            __syncthreads();
            __half* out = g_vh + (size_t)b * CC * NN + n0;
            #pragma unroll
            for (int it = 0; it < 4; it++) {
                int i = tid + it * 256;
                int r = i >> 3, n8 = (i & 7) << 3;
                *(uint4*)(out + (size_t)r * NN + n8) = *(uint4*)&st_h[r * 72 + n8];
            }
        }

        if (m == 0) CPA_WAIT1;
        if (m == 1) CPA_WAIT0;
        __syncthreads();
    }
}

// ============================ flash v8: LDS.64 permuted frags, separate combine ============================
// CTA: 128 q rows (8 warps x m16), 2048 keys in 16 blocks of 128. 256 threads.
// SMEM halves (stride 144): Q[128][144] | K 2x | V 2x = 180 KB
#define FS 144
#define OFFK 18432
#define OFFV 55296
#define FB 18432
#define SMEM_FLASH8 (92160 * 2)
#define ONES2 0x3C003C00u

__global__ __launch_bounds__(256, 1)
void flash8() {
    extern __shared__ __half smh[];
    uint32_t sbase = smem_u32(smh);

    int tid = threadIdx.x;
    int w = tid >> 5, lane = tid & 31;
    int g = lane >> 2, t = lane & 3;
    int qrow = w * 16 + g;

    int qtile = blockIdx.x, half = blockIdx.y, b = blockIdx.z;
    const __half* qg = g_qh + ((size_t)b * NN + (size_t)qtile * 128) * CC;
    const __half* kg = g_kh + ((size_t)b * NN + (size_t)half * 2048) * CC;
    const __half* vg = g_vh + (size_t)b * CC * NN + (size_t)half * 2048;

    // ---- prologue: Q, K0, V0 ----
    #pragma unroll
    for (int it = 0; it < 8; it++) {
        int i = tid + it * 256;
        int r = i >> 4, c16 = i & 15;
        CPA(sbase + (uint32_t)(r * FS * 2 + c16 * 16), qg + (size_t)r * CC + c16 * 8);
    }
    #pragma unroll
    for (int it = 0; it < 8; it++) {
        int i = tid + it * 256;
        int r = i >> 4, c16 = i & 15;
        CPA(sbase + (uint32_t)(OFFK * 2 + r * FS * 2 + c16 * 16), kg + (size_t)r * CC + c16 * 8);
    }
    #pragma unroll
    for (int it = 0; it < 8; it++) {
        int i = tid + it * 256;
        int c = i >> 4, k16 = i & 15;
        CPA(sbase + (uint32_t)(OFFV * 2 + c * FS * 2 + k16 * 16), vg + (size_t)c * NN + k16 * 8);
    }
    CPA_COMMIT;
    CPA_WAIT0;
    __syncthreads();

    // ---- hoist Q fragments via permuted LDS.64 ----
    uint32_t qa[8][4];
    #pragma unroll
    for (int ko = 0; ko < 8; ko++) {
        const __half* qp = smh + qrow * FS + ko * 16;
        uint2 lo = *(const uint2*)(qp + 4 * t);
        uint2 hi = *(const uint2*)(qp + 8 * FS + 4 * t);
        qa[ko][0] = lo.x; qa[ko][2] = lo.y;
        qa[ko][1] = hi.x; qa[ko][3] = hi.y;
    }
    __syncthreads();

    float o[16][4] = {};
    float rsacc[4] = {};

    for (int kb = 0; kb < 16; kb++) {
        int buf = kb & 1;
        if (kb < 15) {
            int m0 = (kb + 1) * 128;
            int nb = buf ^ 1;
            #pragma unroll
            for (int it = 0; it < 8; it++) {
                int i = tid + it * 256;
                int r = i >> 4, c16 = i & 15;
                CPA(sbase + (uint32_t)((OFFK + nb * FB) * 2 + r * FS * 2 + c16 * 16),
                    kg + (size_t)(m0 + r) * CC + c16 * 8);
            }
            #pragma unroll
            for (int it = 0; it < 8; it++) {
                int i = tid + it * 256;
                int c = i >> 4, k16 = i & 15;
                CPA(sbase + (uint32_t)((OFFV + nb * FB) * 2 + c * FS * 2 + k16 * 16),
                    vg + (size_t)c * NN + m0 + k16 * 8);
            }
            CPA_COMMIT;
        }

        const __half* Ks = smh + OFFK + buf * FB;
        const __half* Vs = smh + OFFV + buf * FB;

        // ---- S + exp in two n-halves (sacc stays at 32 regs) ----
        uint32_t pa[8][4];
        #pragma unroll
        for (int nh = 0; nh < 2; nh++) {
            float sacc[8][4] = {};
            #pragma unroll
            for (int ko = 0; ko < 8; ko++) {
                #pragma unroll
                for (int nt = 0; nt < 8; nt++) {
                    const __half* kp = Ks + ((nh * 8 + nt) * 8 + g) * FS + ko * 16;
                    uint2 bb = *(const uint2*)(kp + 4 * t);
                    MMA_F16(sacc[nt], qa[ko], bb.x, bb.y);
                }
            }
            #pragma unroll
            for (int nt = 0; nt < 8; nt++) {
                pa[nh * 4 + (nt >> 1)][(nt & 1) * 2 + 0] =
                    ex2_h2(pack_h2(sacc[nt][0], sacc[nt][1]));
                pa[nh * 4 + (nt >> 1)][(nt & 1) * 2 + 1] =
                    ex2_h2(pack_h2(sacc[nt][2], sacc[nt][3]));
            }
        }

        // ---- rowsums via ones-MMA ----
        #pragma unroll
        for (int kf = 0; kf < 8; kf++)
            MMA_F16(rsacc, pa[kf], ONES2, ONES2);

        // ---- O += P V ----
        #pragma unroll
        for (int kf = 0; kf < 8; kf++) {
            #pragma unroll
            for (int cn = 0; cn < 16; cn++) {
                const __half* vp = Vs + (cn * 8 + g) * FS + kf * 16;
                uint2 bb = *(const uint2*)(vp + 4 * t);
                MMA_F16(o[cn], pa[kf], bb.x, bb.y);
            }
        }

        CPA_WAIT0;
        __syncthreads();
    }

    // ---- rowsums already reduced by MMA ----
    if (t == 0) {
        float* gl = g_lsum + (size_t)half * BB * NN + (size_t)b * NN + qtile * 128;
        gl[qrow] = rsacc[0];
        gl[qrow + 8] = rsacc[2];
    }

    // ---- stage O (f32, stride 132) for coalesced partial writes ----
    float* smf = (float*)smh;
    #pragma unroll
    for (int cn = 0; cn < 16; cn++) {
        int c0 = cn * 8 + 2 * t;
        smf[c0 * 132 + qrow]           = o[cn][0];
        smf[(c0 + 1) * 132 + qrow]     = o[cn][1];
        smf[c0 * 132 + qrow + 8]       = o[cn][2];
        smf[(c0 + 1) * 132 + qrow + 8] = o[cn][3];
    }
    __syncthreads();
    float* gp = g_part + (size_t)half * BB * CC * NN + (size_t)b * CC * NN + (size_t)qtile * 128;
    #pragma unroll
    for (int it = 0; it < 16; it++) {
        int i = tid + it * 256;
        int c = i >> 5, q4 = (i & 31) << 2;
        *(float4*)(gp + (size_t)c * NN + q4) = *(float4*)&smf[c * 132 + q4];
    }
}

// ============================ combine halves ============================
__global__ __launch_bounds__(256)
void combine_kernel(float* __restrict__ out) {
    int idx = blockIdx.x * 256 + threadIdx.x;
    size_t e = (size_t)idx * 4;
    int n = (int)(e & (NN - 1));
    int b = (int)(e / ((size_t)CC * NN));
    float4 p0 = *(const float4*)(g_part + e);
    float4 p1 = *(const float4*)(g_part + (size_t)BB * CC * NN + e);
    float4 l0 = *(const float4*)(g_lsum + (size_t)b * NN + n);
    float4 l1 = *(const float4*)(g_lsum + (size_t)BB * NN + (size_t)b * NN + n);
    float4 o;
    o.x = (p0.x + p1.x) / (l0.x + l1.x);
    o.y = (p0.y + p1.y) / (l0.y + l1.y);
    o.z = (p0.z + p1.z) / (l0.z + l1.z);
    o.w = (p0.w + p1.w) / (l0.w + l1.w);
    *(float4*)(out + e) = o;
}

// ============================ launch ============================
extern "C" void kernel_launch(void* const* d_in, const int* in_sizes, int n_in,
                              void* d_out, int out_size) {
    const float* x  = (const float*)d_in[0];
    const float* Wq = (const float*)d_in[1];
    const float* bq = (const float*)d_in[2];
    const float* Wk = (const float*)d_in[3];
    const float* bk = (const float*)d_in[4];
    const float* Wv = (const float*)d_in[5];
    const float* bv = (const float*)d_in[6];
    float* out = (float*)d_out;

    cudaFuncSetAttribute(qkv5, cudaFuncAttributeMaxDynamicSharedMemorySize, SMEM_QKV);
    dim3 gq(NN / 64, BB);
    qkv5<<<gq, 256, SMEM_QKV>>>(x, Wq, bq, Wk, bk, Wv, bv);

    cudaFuncSetAttribute(flash8, cudaFuncAttributeMaxDynamicSharedMemorySize, SMEM_FLASH8);
    dim3 gf(NN / 128, 2, BB);
    flash8<<<gf, 256, SMEM_FLASH8>>>();

    combine_kernel<<<(BB * CC * NN / 4) / 256, 256>>>(out);
}

// round 13
// speedup vs baseline: 1.4823x; 1.4823x over previous
#include <cuda_runtime.h>
#include <cuda_fp16.h>
#include <cstdint>

#define BB 2
#define CC 128
#define NN 4096
#define LOG2E 1.4426950408889634f

// Device scratch
__device__ __half g_qh[BB * NN * CC];      // [b][n][c]  fp16, pre-scaled by log2e
__device__ __half g_kh[BB * NN * CC];      // [b][n][c]  fp16
__device__ __half g_vh[BB * CC * NN];      // [b][c][n]  fp16
__device__ float g_part[2 * BB * CC * NN]; // [half][b][c][n] partial O
__device__ float g_lsum[2 * BB * NN];      // [half][b][n] partial row sums

// ============================ helpers ============================
__device__ __forceinline__ uint32_t smem_u32(const void* p) {
    uint32_t a;
    asm("{ .reg .u64 t; cvta.to.shared.u64 t, %1; cvt.u32.u64 %0, t; }"
        : "=r"(a) : "l"(p));
    return a;
}
__device__ __forceinline__ uint32_t ex2_h2(uint32_t x) {
    uint32_t r;
    asm("ex2.approx.f16x2 %0, %1;" : "=r"(r) : "r"(x));
    return r;
}
__device__ __forceinline__ uint32_t pack_h2(float lo, float hi) {
    __half2 h = __floats2half2_rn(lo, hi);
    return *reinterpret_cast<uint32_t*>(&h);
}

#define MMA_F16(d, a, b0, b1) \
    asm volatile("mma.sync.aligned.m16n8k16.row.col.f32.f16.f16.f32 " \
        "{%0,%1,%2,%3}, {%4,%5,%6,%7}, {%8,%9}, {%0,%1,%2,%3};" \
        : "+f"((d)[0]), "+f"((d)[1]), "+f"((d)[2]), "+f"((d)[3]) \
        : "r"((a)[0]), "r"((a)[1]), "r"((a)[2]), "r"((a)[3]), "r"(b0), "r"(b1))

// ldmatrix x4: B-frags for TWO n8xk16 mma tiles in one instruction
#define LDSM_X4(r0, r1, r2, r3, addr) \
    asm volatile("ldmatrix.sync.aligned.m8n8.x4.shared.b16 {%0,%1,%2,%3}, [%4];" \
        : "=r"(r0), "=r"(r1), "=r"(r2), "=r"(r3) : "r"(addr))

#define CPA(dst, src) \
    asm volatile("cp.async.cg.shared.global [%0], [%1], 16;" :: "r"(dst), "l"(src))
#define CPA_COMMIT asm volatile("cp.async.commit_group;" ::: "memory")
#define CPA_WAIT0  asm volatile("cp.async.wait_group 0;" ::: "memory")
#define CPA_WAIT1  asm volatile("cp.async.wait_group 1;" ::: "memory")

// ============================ QKV: merged 1-wave, 3xFP16 split GEMM (R10 proven) ============================
#define WS 132
#define OFF_W1  16896
#define OFF_XF  33792
#define OFF_XHI 43008
#define OFF_XLO 47360
#define SMEM_QKV (51712 * 4)
#define INV64 0.015625f

__global__ __launch_bounds__(256, 1)
void qkv5(const float* __restrict__ x,
          const float* __restrict__ Wq, const float* __restrict__ bq,
          const float* __restrict__ Wk, const float* __restrict__ bk,
          const float* __restrict__ Wv, const float* __restrict__ bv) {
    extern __shared__ float sm[];
    uint32_t sbase = smem_u32(sm);

    int n0 = blockIdx.x * 64;
    int b = blockIdx.y;
    const float* xb = x + (size_t)b * CC * NN;
    const float* Bm[3] = {bq, bk, bv};

    int tid = threadIdx.x;
    int w = tid >> 5, lane = tid & 31;
    int g = lane >> 2, t = lane & 3;
    int crow = w * 16 + g;

    // ---- prologue: W0(Wq) | X | W1(Wk) in separate groups ----
    #pragma unroll
    for (int it = 0; it < 16; it++) {
        int i = tid + it * 256;
        int r = i >> 5, c4 = (i & 31) << 2;
        CPA(sbase + (uint32_t)(r * WS + c4) * 4, Wq + (size_t)r * CC + c4);
    }
    CPA_COMMIT;
    #pragma unroll
    for (int it = 0; it < 8; it++) {
        int i = tid + it * 256;
        int r = i >> 4, n4 = (i & 15) << 2;
        CPA(sbase + (uint32_t)(OFF_XF + r * 72 + n4) * 4, xb + (size_t)r * NN + n0 + n4);
    }
    CPA_COMMIT;
    #pragma unroll
    for (int it = 0; it < 16; it++) {
        int i = tid + it * 256;
        int r = i >> 5, c4 = (i & 31) << 2;
        CPA(sbase + (uint32_t)(OFF_W1 + r * WS + c4) * 4, Wk + (size_t)r * CC + c4);
    }
    CPA_COMMIT;

    CPA_WAIT1;
    __syncthreads();

    // ---- convert X -> transposed fp16 hi/lo tiles [n][k], stride 136 halves ----
    {
        int n = tid >> 2;
        int kbase = (tid & 3) * 32;
        uint32_t* XhiT = (uint32_t*)sm + OFF_XHI;
        uint32_t* XloT = (uint32_t*)sm + OFF_XLO;
        #pragma unroll
        for (int j = 0; j < 16; j++) {
            int k = kbase + 2 * j;
            float f0 = sm[OFF_XF + k * 72 + n];
            float f1 = sm[OFF_XF + (k + 1) * 72 + n];
            __half h0 = __float2half_rn(f0), h1 = __float2half_rn(f1);
            uint32_t hi = pack_h2(__half2float(h0), __half2float(h1));
            uint32_t lo = pack_h2(f0 - __half2float(h0), f1 - __half2float(h1));
            XhiT[n * 68 + (kbase >> 1) + j] = hi;
            XloT[n * 68 + (kbase >> 1) + j] = lo;
        }
    }
    __syncthreads();

    const uint32_t* Xhi = (const uint32_t*)sm + OFF_XHI;
    const uint32_t* Xlo = (const uint32_t*)sm + OFF_XLO;

    #pragma unroll 1
    for (int m = 0; m < 3; m++) {
        const float* Wb = sm + ((m & 1) ? OFF_W1 : 0);

        // ---- hoist W fp16 hi/lo A-frags (scaled x64) ----
        uint32_t wa_hi[8][4], wa_lo[8][4];
        #pragma unroll
        for (int ko = 0; ko < 8; ko++) {
            #pragma unroll
            for (int q = 0; q < 4; q++) {
                int row = crow + ((q & 1) ? 8 : 0);
                int kk = ko * 16 + 2 * t + ((q >> 1) ? 8 : 0);
                float2 p = *(const float2*)&Wb[row * WS + kk];
                p.x *= 64.0f; p.y *= 64.0f;
                __half h0 = __float2half_rn(p.x), h1 = __float2half_rn(p.y);
                wa_hi[ko][q] = pack_h2(__half2float(h0), __half2float(h1));
                wa_lo[ko][q] = pack_h2(p.x - __half2float(h0), p.y - __half2float(h1));
            }
        }
        __syncthreads();

        if (m == 0) {
            #pragma unroll
            for (int it = 0; it < 16; it++) {
                int i = tid + it * 256;
                int r = i >> 5, c4 = (i & 31) << 2;
                CPA(sbase + (uint32_t)(r * WS + c4) * 4, Wv + (size_t)r * CC + c4);
            }
            CPA_COMMIT;
        }

        // ---- 3xFP16 GEMM ----
        float acc[8][4] = {};
        #pragma unroll
        for (int ko = 0; ko < 8; ko++) {
            #pragma unroll
            for (int nt = 0; nt < 8; nt++) {
                int i0 = (nt * 8 + g) * 68 + ko * 8 + t;
                uint32_t bh0 = Xhi[i0], bh1 = Xhi[i0 + 4];
                uint32_t bl0 = Xlo[i0], bl1 = Xlo[i0 + 4];
                MMA_F16(acc[nt], wa_lo[ko], bh0, bh1);
                MMA_F16(acc[nt], wa_hi[ko], bl0, bl1);
                MMA_F16(acc[nt], wa_hi[ko], bh0, bh1);
            }
        }
        __syncthreads();

        const float* bias = Bm[m];
        float b0v = bias[crow], b1v = bias[crow + 8];
        float qs = (m == 0) ? LOG2E : 1.0f;
        __half* st_h = (__half*)(sm + OFF_XF);

        if (m != 2) {
            // q,k: stage fp16 [n][c] stride 136
            #pragma unroll
            for (int nt = 0; nt < 8; nt++) {
                int n = nt * 8 + 2 * t;
                st_h[n * 136 + crow]           = __float2half_rn((acc[nt][0] * INV64 + b0v) * qs);
                st_h[(n + 1) * 136 + crow]     = __float2half_rn((acc[nt][1] * INV64 + b0v) * qs);
                st_h[n * 136 + crow + 8]       = __float2half_rn((acc[nt][2] * INV64 + b1v) * qs);
                st_h[(n + 1) * 136 + crow + 8] = __float2half_rn((acc[nt][3] * INV64 + b1v) * qs);
            }
            __syncthreads();
            __half* out = ((m == 0) ? g_qh : g_kh) + ((size_t)b * NN + n0) * CC;
            #pragma unroll
            for (int it = 0; it < 4; it++) {
                int i = tid + it * 256;
                int r = i >> 4, c8 = (i & 15) << 3;
                *(uint4*)(out + (size_t)r * CC + c8) = *(uint4*)&st_h[r * 136 + c8];
            }
        } else {
            // v: stage fp16 [c][n] stride 72
            #pragma unroll
            for (int nt = 0; nt < 8; nt++) {
                int n = nt * 8 + 2 * t;
                *(__half2*)&st_h[crow * 72 + n] =
                    __floats2half2_rn(acc[nt][0] * INV64 + b0v, acc[nt][1] * INV64 + b0v);
                *(__half2*)&st_h[(crow + 8) * 72 + n] =
                    __floats2half2_rn(acc[nt][2] * INV64 + b1v, acc[nt][3] * INV64 + b1v);
            }
            __syncthreads();
            __half* out = g_vh + (size_t)b * CC * NN + n0;
            #pragma unroll
            for (int it = 0; it < 4; it++) {
                int i = tid + it * 256;
                int r = i >> 3, n8 = (i & 7) << 3;
                *(uint4*)(out + (size_t)r * NN + n8) = *(uint4*)&st_h[r * 72 + n8];
            }
        }

        if (m == 0) CPA_WAIT1;
        if (m == 1) CPA_WAIT0;
        __syncthreads();
    }
}

// ============================ flash v9: R10 structure + ldmatrix B-frags ============================
// CTA: 128 q rows (8 warps x m16), 2048 keys in 16 blocks of 128. 256 threads.
// SMEM halves (stride 136): Q[128][136] | K 2x | V 2x = 170 KB
#define FS 136
#define OFFK 17408
#define OFFV 52224
#define FB 17408
#define SMEM_FLASH9 (87040 * 2)
#define ONES2 0x3C003C00u

__global__ __launch_bounds__(256, 1)
void flash9() {
    extern __shared__ __half smh[];
    uint32_t sbase = smem_u32(smh);

    int tid = threadIdx.x;
    int w = tid >> 5, lane = tid & 31;
    int g = lane >> 2, t = lane & 3;
    int qrow = w * 16 + g;

    // ldmatrix per-lane offset: matrices (r0..r3) = (n0,k0),(n0,k0+8),(n0+8,k0),(n0+8,k0+8)
    int lrow = (lane & 7) + ((lane >> 4) & 1) * 8;   // row within 16-row group
    int lkof = ((lane >> 3) & 1) * 8;                // k offset 0/8
    uint32_t laneoff = (uint32_t)(lrow * FS + lkof) * 2;

    int qtile = blockIdx.x, half = blockIdx.y, b = blockIdx.z;
    const __half* qg = g_qh + ((size_t)b * NN + (size_t)qtile * 128) * CC;
    const __half* kg = g_kh + ((size_t)b * NN + (size_t)half * 2048) * CC;
    const __half* vg = g_vh + (size_t)b * CC * NN + (size_t)half * 2048;

    // ---- prologue: Q, K0, V0 ----
    #pragma unroll
    for (int it = 0; it < 8; it++) {
        int i = tid + it * 256;
        int r = i >> 4, c16 = i & 15;
        CPA(sbase + (uint32_t)(r * FS * 2 + c16 * 16), qg + (size_t)r * CC + c16 * 8);
    }
    #pragma unroll
    for (int it = 0; it < 8; it++) {
        int i = tid + it * 256;
        int r = i >> 4, c16 = i & 15;
        CPA(sbase + (uint32_t)(OFFK * 2 + r * FS * 2 + c16 * 16), kg + (size_t)r * CC + c16 * 8);
    }
    #pragma unroll
    for (int it = 0; it < 8; it++) {
        int i = tid + it * 256;
        int c = i >> 4, k16 = i & 15;
        CPA(sbase + (uint32_t)(OFFV * 2 + c * FS * 2 + k16 * 16), vg + (size_t)c * NN + k16 * 8);
    }
    CPA_COMMIT;
    CPA_WAIT0;
    __syncthreads();

    // ---- hoist Q fragments: m16 x k128 fp16 = 32 regs (one-time) ----
    uint32_t qa[8][4];
    #pragma unroll
    for (int ko = 0; ko < 8; ko++) {
        const __half* qp = smh + qrow * FS + ko * 16;
        qa[ko][0] = *(const uint32_t*)(qp + 2 * t);
        qa[ko][1] = *(const uint32_t*)(qp + 8 * FS + 2 * t);
        qa[ko][2] = *(const uint32_t*)(qp + 2 * t + 8);
        qa[ko][3] = *(const uint32_t*)(qp + 8 * FS + 2 * t + 8);
    }
    __syncthreads();

    float o[16][4] = {};
    float rsacc[4] = {};

    for (int kb = 0; kb < 16; kb++) {
        int buf = kb & 1;
        if (kb < 15) {
            int m0 = (kb + 1) * 128;
            int nb = buf ^ 1;
            #pragma unroll
            for (int it = 0; it < 8; it++) {
                int i = tid + it * 256;
                int r = i >> 4, c16 = i & 15;
                CPA(sbase + (uint32_t)((OFFK + nb * FB) * 2 + r * FS * 2 + c16 * 16),
                    kg + (size_t)(m0 + r) * CC + c16 * 8);
            }
            #pragma unroll
            for (int it = 0; it < 8; it++) {
                int i = tid + it * 256;
                int c = i >> 4, k16 = i & 15;
                CPA(sbase + (uint32_t)((OFFV + nb * FB) * 2 + c * FS * 2 + k16 * 16),
                    vg + (size_t)c * NN + m0 + k16 * 8);
            }
            CPA_COMMIT;
        }

        uint32_t kaddr = sbase + (uint32_t)(OFFK + buf * FB) * 2 + laneoff;
        uint32_t vaddr = sbase + (uint32_t)(OFFV + buf * FB) * 2 + laneoff;

        // ---- S + exp in two n-halves (sacc stays at 32 regs) ----
        uint32_t pa[8][4];
        #pragma unroll
        for (int nh = 0; nh < 2; nh++) {
            float sacc[8][4] = {};
            #pragma unroll
            for (int ko = 0; ko < 8; ko++) {
                #pragma unroll
                for (int np = 0; np < 4; np++) {    // n16 groups
                    uint32_t a = kaddr + (uint32_t)(((nh * 4 + np) * 16) * FS + ko * 16) * 2;
                    uint32_t r0, r1, r2, r3;
                    LDSM_X4(r0, r1, r2, r3, a);
                    MMA_F16(sacc[np * 2 + 0], qa[ko], r0, r1);
                    MMA_F16(sacc[np * 2 + 1], qa[ko], r2, r3);
                }
            }
            #pragma unroll
            for (int nt = 0; nt < 8; nt++) {
                pa[nh * 4 + (nt >> 1)][(nt & 1) * 2 + 0] =
                    ex2_h2(pack_h2(sacc[nt][0], sacc[nt][1]));
                pa[nh * 4 + (nt >> 1)][(nt & 1) * 2 + 1] =
                    ex2_h2(pack_h2(sacc[nt][2], sacc[nt][3]));
            }
        }

        // ---- rowsums via ones-MMA ----
        #pragma unroll
        for (int kf = 0; kf < 8; kf++)
            MMA_F16(rsacc, pa[kf], ONES2, ONES2);

        // ---- O += P V (ldmatrix x4 per c16 group) ----
        #pragma unroll
        for (int kf = 0; kf < 8; kf++) {
            #pragma unroll
            for (int cp = 0; cp < 8; cp++) {        // c16 groups
                uint32_t a = vaddr + (uint32_t)((cp * 16) * FS + kf * 16) * 2;
                uint32_t r0, r1, r2, r3;
                LDSM_X4(r0, r1, r2, r3, a);
                MMA_F16(o[cp * 2 + 0], pa[kf], r0, r1);
                MMA_F16(o[cp * 2 + 1], pa[kf], r2, r3);
            }
        }

        CPA_WAIT0;
        __syncthreads();
    }

    // ---- rowsums already reduced by MMA ----
    if (t == 0) {
        float* gl = g_lsum + (size_t)half * BB * NN + (size_t)b * NN + qtile * 128;
        gl[qrow] = rsacc[0];
        gl[qrow + 8] = rsacc[2];
    }

    // ---- stage O (f32, stride 132) for coalesced partial writes ----
    float* smf = (float*)smh;
    #pragma unroll
    for (int cn = 0; cn < 16; cn++) {
        int c0 = cn * 8 + 2 * t;
        smf[c0 * 132 + qrow]           = o[cn][0];
        smf[(c0 + 1) * 132 + qrow]     = o[cn][1];
        smf[c0 * 132 + qrow + 8]       = o[cn][2];
        smf[(c0 + 1) * 132 + qrow + 8] = o[cn][3];
    }
    __syncthreads();
    float* gp = g_part + (size_t)half * BB * CC * NN + (size_t)b * CC * NN + (size_t)qtile * 128;
    #pragma unroll
    for (int it = 0; it < 16; it++) {
        int i = tid + it * 256;
        int c = i >> 5, q4 = (i & 31) << 2;
        *(float4*)(gp + (size_t)c * NN + q4) = *(float4*)&smf[c * 132 + q4];
    }
}

// ============================ combine halves ============================
__global__ __launch_bounds__(256)
void combine_kernel(float* __restrict__ out) {
    int idx = blockIdx.x * 256 + threadIdx.x;
    size_t e = (size_t)idx * 4;
    int n = (int)(e & (NN - 1));
    int b = (int)(e / ((size_t)CC * NN));
    float4 p0 = *(const float4*)(g_part + e);
    float4 p1 = *(const float4*)(g_part + (size_t)BB * CC * NN + e);
    float4 l0 = *(const float4*)(g_lsum + (size_t)b * NN + n);
    float4 l1 = *(const float4*)(g_lsum + (size_t)BB * NN + (size_t)b * NN + n);
    float4 o;
    o.x = (p0.x + p1.x) / (l0.x + l1.x);
    o.y = (p0.y + p1.y) / (l0.y + l1.y);
    o.z = (p0.z + p1.z) / (l0.z + l1.z);
    o.w = (p0.w + p1.w) / (l0.w + l1.w);
    *(float4*)(out + e) = o;
}

// ============================ launch ============================
extern "C" void kernel_launch(void* const* d_in, const int* in_sizes, int n_in,
                              void* d_out, int out_size) {
    const float* x  = (const float*)d_in[0];
    const float* Wq = (const float*)d_in[1];
    const float* bq = (const float*)d_in[2];
    const float* Wk = (const float*)d_in[3];
    const float* bk = (const float*)d_in[4];
    const float* Wv = (const float*)d_in[5];
    const float* bv = (const float*)d_in[6];
    float* out = (float*)d_out;

    cudaFuncSetAttribute(qkv5, cudaFuncAttributeMaxDynamicSharedMemorySize, SMEM_QKV);
    dim3 gq(NN / 64, BB);
    qkv5<<<gq, 256, SMEM_QKV>>>(x, Wq, bq, Wk, bk, Wv, bv);

    cudaFuncSetAttribute(flash9, cudaFuncAttributeMaxDynamicSharedMemorySize, SMEM_FLASH9);
    dim3 gf(NN / 128, 2, BB);
    flash9<<<gf, 256, SMEM_FLASH9>>>();

    combine_kernel<<<(BB * CC * NN / 4) / 256, 256>>>(out);
}